// round 5
// baseline (speedup 1.0000x reference)
#include <cuda_runtime.h>
#include <cuda_bf16.h>

#define VOCAB 50257
#define BATCH 512
#define SEQ   512

// One warp per row. 16 coalesced id loads up-front, 32 independent gathers,
// pure-shuffle reduction, single float2 store. No smem, no __syncthreads,
// single kernel launch.
__global__ __launch_bounds__(32) void bow_logits_kernel(
    const int*   __restrict__ ids,
    const float* __restrict__ W,     // [2, VOCAB]
    const float* __restrict__ bias,  // [2]
    float*       __restrict__ out)   // [BATCH, 2]
{
    const int row  = blockIdx.x;
    const int lane = threadIdx.x;
    const int base = (row << 9) + lane;

    // 16 independent coalesced id loads (front-batched -> MLP 16).
    int id[16];
    #pragma unroll
    for (int i = 0; i < 16; i++)
        id[i] = __ldg(ids + base + i * 32);

    // 32 independent predicated gathers (2 per token), batched before any add.
    float a[16], b[16];
    #pragma unroll
    for (int i = 0; i < 16; i++) {
        a[i] = (id[i] != 0) ? __ldg(W + id[i])         : 0.f;
        b[i] = (id[i] != 0) ? __ldg(W + VOCAB + id[i]) : 0.f;
    }

    // Pairwise sum tree.
    float s0 = 0.f, s1 = 0.f;
    #pragma unroll
    for (int i = 0; i < 8; i++) {
        s0 += a[2 * i] + a[2 * i + 1];
        s1 += b[2 * i] + b[2 * i + 1];
    }

    // Warp reduction — the only reduction stage.
    #pragma unroll
    for (int o = 16; o > 0; o >>= 1) {
        s0 += __shfl_down_sync(0xffffffffu, s0, o);
        s1 += __shfl_down_sync(0xffffffffu, s1, o);
    }

    if (lane == 0) {
        float2 r;
        r.x = s0 + __ldg(bias + 0);
        r.y = s1 + __ldg(bias + 1);
        *reinterpret_cast<float2*>(out + row * 2) = r;
    }
}

extern "C" void kernel_launch(void* const* d_in, const int* in_sizes, int n_in,
                              void* d_out, int out_size) {
    const int*   ids  = (const int*)  d_in[0];  // input_ids [512, 512] int32
    const float* W    = (const float*)d_in[1];  // W [2, 50257] fp32
    const float* bias = (const float*)d_in[2];  // b [2] fp32
    float*       out  = (float*)d_out;          // logits [512, 2] fp32

    bow_logits_kernel<<<BATCH, 32>>>(ids, W, bias, out);
}